// round 11
// baseline (speedup 1.0000x reference)
#include <cuda_runtime.h>
#include <math.h>

#define NT 2000
#define NPT 255
#define NC 16
#define NM 32
#define NG 16
#define PGRID 296                     // persistent grid: 2 CTAs/SM x 148 SMs
#define NHALF (2*PGRID)               // 592 independent half-CTA tree streams

typedef unsigned long long ull;

// slots: 40 x 256 floats (40KB). half h owns slots [20h, 20h+20):
//   sng0 scratch: +0..8, sng1 scratch: +8..16, L2 betas: +16+ss (ss=0..3),
//   L1 pairsum reuses slot +0 (after L2 extraction).
#define W_FLOATS (40*256)
#define BF_OFF  W_FLOATS
#define PB_OFF  (BF_OFF + NM*NG*NC)
#define NUL_OFF (PB_OFF + NM*NG*NC)
#define DYN_FLOATS (NUL_OFF + NM*NG)
#define DYN_BYTES  (DYN_FLOATS*4)     // 108544 B -> 2 CTAs/SM

__device__ float g_smA[NC*NC*NG];     // softmaxed A, [p][c][g]
__device__ float g_smBf[NM*NG*NC];    // softmaxed B, [m][g][c]
__device__ float g_smPi[NC*NG];       // softmaxed Pi, [c][g]
__device__ float g_PiBn[NM*NG*NC];    // normalized leaf beta, [m][g][c]
__device__ float g_nuLog[NM*NG];      // log2 nu per (m,g)

// ---------------------------------------------------------------------------
// packed f32x2 helpers (FFMA2/FADD2 only reachable via PTX)
// ---------------------------------------------------------------------------
__device__ __forceinline__ ull pack2(float lo, float hi) {
    ull r; asm("mov.b64 %0, {%1, %2};" : "=l"(r) : "f"(lo), "f"(hi)); return r;
}
__device__ __forceinline__ void ffma2(ull& d, ull a, ull b) {
    asm("fma.rn.f32x2 %0, %1, %2, %0;" : "+l"(d) : "l"(a), "l"(b));
}
__device__ __forceinline__ void fadd2(ull& d, ull a) {
    asm("add.rn.f32x2 %0, %0, %1;" : "+l"(d) : "l"(a));
}
__device__ __forceinline__ float unpack_sum(ull v) {
    float lo, hi; asm("mov.b64 {%0, %1}, %2;" : "=f"(lo), "=f"(hi) : "l"(v));
    return lo + hi;
}
#define HBAR(id) asm volatile("bar.sync %0, 128;" :: "r"(id) : "memory")

// ---------------------------------------------------------------------------
// Prologue: softmaxes + emission table + normalized leaf table + log2 nu.
// ---------------------------------------------------------------------------
__global__ void htmm_softmax_kernel(const float* __restrict__ A,
                                    const float* __restrict__ B,
                                    const float* __restrict__ Pi) {
    int tid = threadIdx.x;
    int c = tid >> 4;
    int g = tid & 15;
    {   // A: softmax over p for each (c,g)
        float mx = -1e30f;
        #pragma unroll
        for (int p = 0; p < NC; p++) mx = fmaxf(mx, A[p*NC*NG + c*NG + g]);
        float e[NC]; float s = 0.f;
        #pragma unroll
        for (int p = 0; p < NC; p++) { e[p] = expf(A[p*NC*NG + c*NG + g] - mx); s += e[p]; }
        float rs = 1.f / s;
        #pragma unroll
        for (int p = 0; p < NC; p++) g_smA[p*NC*NG + c*NG + g] = e[p] * rs;
    }
    {   // B: softmax over m for each (c,g); store [m][g][c]
        float mx = -1e30f;
        #pragma unroll
        for (int m = 0; m < NM; m++) mx = fmaxf(mx, B[c*NM*NG + m*NG + g]);
        float s = 0.f;
        #pragma unroll
        for (int m = 0; m < NM; m++) s += expf(B[c*NM*NG + m*NG + g] - mx);
        float rs = 1.f / s;
        #pragma unroll
        for (int m = 0; m < NM; m++)
            g_smBf[m*NG*NC + g*NC + c] = expf(B[c*NM*NG + m*NG + g] - mx) * rs;
    }
    if (tid < NG) {   // Pi: softmax over c for each g
        int gg = tid;
        float mx = -1e30f;
        #pragma unroll
        for (int cc = 0; cc < NC; cc++) mx = fmaxf(mx, Pi[cc*NG + gg]);
        float s = 0.f;
        #pragma unroll
        for (int cc = 0; cc < NC; cc++) s += expf(Pi[cc*NG + gg] - mx);
        float rs = 1.f / s;
        #pragma unroll
        for (int cc = 0; cc < NC; cc++)
            g_smPi[cc*NG + gg] = expf(Pi[cc*NG + gg] - mx) * rs;
    }
    __syncthreads();
    // per (m,g): v = Pi*B; nu = sum v; PiBn = v/nu; log2 nu
    for (int i = tid; i < NM*NG; i += 256) {
        int m = i >> 4, gg = i & 15;
        float v[NC]; float nu = 0.f;
        #pragma unroll
        for (int cc = 0; cc < NC; cc++) {
            v[cc] = g_smPi[cc*NG + gg] * g_smBf[m*NG*NC + gg*NC + cc];
            nu += v[cc];
        }
        float rnu = 1.f / nu;
        #pragma unroll
        for (int cc = 0; cc < NC; cc++)
            g_PiBn[m*NG*NC + gg*NC + cc] = v[cc] * rnu;
        g_nuLog[i] = log2f(nu);
    }
}

// ---------------------------------------------------------------------------
// Main kernel: PERSISTENT, TWO INDEPENDENT 128-THREAD TREE STREAMS PER CTA.
// Stream hid = 2*blockIdx.x + h processes trees hid, hid+592, ...
// Within a stream: sng = (tid>>6)&1 owns L2-subtrees {2sng, 2sng+1}
// (processed sequentially, barrier-free); named barrier (id 1+h, 128 thr)
// separates stage/compute/tail. No full-CTA syncs inside the loop.
// pblk = tid&3 (states p = 4*pblk..+3), g = (tid>>2)&15.
// ---------------------------------------------------------------------------
__global__ void __launch_bounds__(256, 2)
htmm_upward_kernel(const int* __restrict__ x, float* __restrict__ out) {
    extern __shared__ __align__(16) float sm[];
    float* sW   = sm;                  // 40 slots x 256 floats
    float* sBf  = sm + BF_OFF;         // [m][g][c]
    float* sPB  = sm + PB_OFF;         // [m][g][c]
    float* sNuL = sm + NUL_OFF;        // [m*NG+g]
    __shared__ int   sx[2][NPT];
    __shared__ float sacc[256];

    const int tid  = threadIdx.x;
    const int h    = tid >> 7;                     // half/stream within CTA
    const int tl   = tid & 127;                    // tid within stream
    const int pblk = tid & 3;
    const int g    = (tid >> 2) & 15;
    const int sng  = (tid >> 6) & 1;               // subtree-group within stream
    const int rowoff  = g*16;
    const int scratch = (20*h + 8*sng)*256;        // 8-slot scratch base (floats)
    const int l2bBase = (20*h + 16)*256;           // 4 L2-beta slots
    const int l1slot  = (20*h)*256;                // L1 pairsum (reuses sng0 scratch)
    const int barid   = 1 + h;

    // ---- stage tables ONCE, full CTA (A via sW scratch; consumed to regs) ----
    for (int i = tid; i < NC*NC*NG; i += 256)  sW[i]  = g_smA[i];
    for (int i = tid; i < NM*NG*NC; i += 256)  sBf[i] = g_smBf[i];
    for (int i = tid; i < NM*NG*NC; i += 256)  sPB[i] = g_PiBn[i];
    for (int i = tid; i < NM*NG; i += 256)     sNuL[i] = g_nuLog[i];
    __syncthreads();

    ull A2[4][8];
    #pragma unroll
    for (int ip = 0; ip < 4; ip++) {
        int p = 4*pblk + ip;
        #pragma unroll
        for (int c2 = 0; c2 < 8; c2++)
            A2[ip][c2] = pack2(sW[p*256 + (2*c2)*16 + g],
                               sW[p*256 + (2*c2+1)*16 + g]);
    }
    __syncthreads();   // sW scratch free; streams diverge after this point

    const int hid = 2*blockIdx.x + h;
    for (int tree = hid; tree < NT; tree += NHALF) {
        HBAR(barid);                                // prev tree fully done
        for (int i = tl; i < NPT; i += 128) sx[h][i] = x[tree*NPT + i];
        HBAR(barid);
        const int* sxh = sx[h];

        float accll = 0.f;   // log2 units

        // ====== two L2-subtrees per sng-group, barrier-free ======
        #pragma unroll 1
        for (int sub = 0; sub < 2; sub++) {
            const int ss = 2*sng + sub;             // L2-subtree index 0..3

            // ---- Level 6 (leaves fused): 8 parents k -> scratch slots ----
            for (int k = 0; k < 8; k++) {
                float wo0 = 0.f, wo1 = 0.f, wo2 = 0.f, wo3 = 0.f;
                #pragma unroll
                for (int sel = 0; sel < 2; sel++) {
                    const int j  = 2*k + sel;               // local L6 node 0..15
                    const int lf = 127 + 32*ss + 2*j;
                    const int m0 = sxh[lf], m1 = sxh[lf + 1];
                    const ull* b0 = (const ull*)(sPB + m0*256 + rowoff);
                    const ull* b1 = (const ull*)(sPB + m1*256 + rowoff);
                    ull a0 = 0ull, a1 = 0ull, a2 = 0ull, a3 = 0ull;
                    #pragma unroll
                    for (int c2 = 0; c2 < 8; c2++) {
                        ull w = b0[c2];
                        fadd2(w, b1[c2]);        // beta_leaf0 + beta_leaf1 (exact)
                        ffma2(a0, A2[0][c2], w);
                        ffma2(a1, A2[1][c2], w);
                        ffma2(a2, A2[2][c2], w);
                        ffma2(a3, A2[3][c2], w);
                    }
                    accll += 0.25f * (sNuL[m0*NG + g] + sNuL[m1*NG + g]);

                    const int mu = sxh[63 + 16*ss + j];
                    const float4 e4 = *(const float4*)(sBf + mu*256 + rowoff + 4*pblk);
                    float bv0 = e4.x * unpack_sum(a0);
                    float bv1 = e4.y * unpack_sum(a1);
                    float bv2 = e4.z * unpack_sum(a2);
                    float bv3 = e4.w * unpack_sum(a3);
                    float s = (bv0 + bv1) + (bv2 + bv3);
                    s += __shfl_xor_sync(0xffffffffu, s, 1);
                    s += __shfl_xor_sync(0xffffffffu, s, 2);
                    float rs = __fdividef(1.f, s);
                    wo0 += bv0*rs; wo1 += bv1*rs; wo2 += bv2*rs; wo3 += bv3*rs;
                    accll += 0.25f * __log2f(s);
                }
                *(float4*)(sW + scratch + k*256 + rowoff + 4*pblk) =
                    make_float4(wo0, wo1, wo2, wo3);
            }

            // ---- Levels 5..3 (in-place, stride doubling) ----
            #pragma unroll 1
            for (int l = 5; l >= 3; l--) {
                const int nParL = 1 << (l - 3);          // 4, 2, 1
                const int st    = 1 << (5 - l);          // 1, 2, 4
                const int nbase = (1 << l) - 1 + (1 << (l - 2))*ss;
                for (int k = 0; k < nParL; k++) {
                    float wo0 = 0.f, wo1 = 0.f, wo2 = 0.f, wo3 = 0.f;
                    #pragma unroll
                    for (int sel = 0; sel < 2; sel++) {
                        const int j = 2*k + sel;
                        const ull* wv = (const ull*)(sW + scratch + j*st*256 + rowoff);
                        ull a0 = 0ull, a1 = 0ull, a2 = 0ull, a3 = 0ull;
                        #pragma unroll
                        for (int c2 = 0; c2 < 8; c2++) {
                            ull w = wv[c2];              // pre-summed sibling pair
                            ffma2(a0, A2[0][c2], w);
                            ffma2(a1, A2[1][c2], w);
                            ffma2(a2, A2[2][c2], w);
                            ffma2(a3, A2[3][c2], w);
                        }
                        const int mu = sxh[nbase + j];
                        const float4 e4 = *(const float4*)(sBf + mu*256 + rowoff + 4*pblk);
                        float bv0 = e4.x * unpack_sum(a0);
                        float bv1 = e4.y * unpack_sum(a1);
                        float bv2 = e4.z * unpack_sum(a2);
                        float bv3 = e4.w * unpack_sum(a3);
                        float s = (bv0 + bv1) + (bv2 + bv3);
                        s += __shfl_xor_sync(0xffffffffu, s, 1);
                        s += __shfl_xor_sync(0xffffffffu, s, 2);
                        // true nu = s/2; /2 cancels, -1 folded at end
                        float rs = __fdividef(1.f, s);
                        wo0 += bv0*rs; wo1 += bv1*rs; wo2 += bv2*rs; wo3 += bv3*rs;
                        accll += 0.25f * __log2f(s);
                    }
                    *(float4*)(sW + scratch + 2*k*st*256 + rowoff + 4*pblk) =
                        make_float4(wo0, wo1, wo2, wo3);
                }
            }

            // ---- L2 node: normalized beta -> L2-beta slot ss ----
            {
                const ull* wv = (const ull*)(sW + scratch + rowoff);   // L3 pairsum
                ull a0 = 0ull, a1 = 0ull, a2 = 0ull, a3 = 0ull;
                #pragma unroll
                for (int c2 = 0; c2 < 8; c2++) {
                    ull w = wv[c2];
                    ffma2(a0, A2[0][c2], w);
                    ffma2(a1, A2[1][c2], w);
                    ffma2(a2, A2[2][c2], w);
                    ffma2(a3, A2[3][c2], w);
                }
                const int mu = sxh[3 + ss];
                const float4 e4 = *(const float4*)(sBf + mu*256 + rowoff + 4*pblk);
                float bv0 = e4.x * unpack_sum(a0);
                float bv1 = e4.y * unpack_sum(a1);
                float bv2 = e4.z * unpack_sum(a2);
                float bv3 = e4.w * unpack_sum(a3);
                float s = (bv0 + bv1) + (bv2 + bv3);
                s += __shfl_xor_sync(0xffffffffu, s, 1);
                s += __shfl_xor_sync(0xffffffffu, s, 2);
                float rs = __fdividef(1.f, s);
                *(float4*)(sW + l2bBase + ss*256 + rowoff + 4*pblk) =
                    make_float4(bv0*rs, bv1*rs, bv2*rs, bv3*rs);
                accll += 0.25f * __log2f(s);
            }
        }

        HBAR(barid);   // all 4 L2 betas of this stream visible

        // ---- L1 + root: sng0 of the stream only ----
        if (sng == 0) {
            float wo0 = 0.f, wo1 = 0.f, wo2 = 0.f, wo3 = 0.f;
            #pragma unroll
            for (int sel = 0; sel < 2; sel++) {
                const ull* r0 = (const ull*)(sW + l2bBase + (2*sel)*256 + rowoff);
                const ull* r1 = (const ull*)(sW + l2bBase + (2*sel+1)*256 + rowoff);
                ull a0 = 0ull, a1 = 0ull, a2 = 0ull, a3 = 0ull;
                #pragma unroll
                for (int c2 = 0; c2 < 8; c2++) {
                    ull w = r0[c2];
                    fadd2(w, r1[c2]);                    // beta_L2 pairsum
                    ffma2(a0, A2[0][c2], w);
                    ffma2(a1, A2[1][c2], w);
                    ffma2(a2, A2[2][c2], w);
                    ffma2(a3, A2[3][c2], w);
                }
                const int mu = sxh[1 + sel];
                const float4 e4 = *(const float4*)(sBf + mu*256 + rowoff + 4*pblk);
                float bv0 = e4.x * unpack_sum(a0);
                float bv1 = e4.y * unpack_sum(a1);
                float bv2 = e4.z * unpack_sum(a2);
                float bv3 = e4.w * unpack_sum(a3);
                float s = (bv0 + bv1) + (bv2 + bv3);
                s += __shfl_xor_sync(0xffffffffu, s, 1);
                s += __shfl_xor_sync(0xffffffffu, s, 2);
                float rs = __fdividef(1.f, s);
                wo0 += bv0*rs; wo1 += bv1*rs; wo2 += bv2*rs; wo3 += bv3*rs;
                accll += 0.25f * __log2f(s);
            }
            *(float4*)(sW + l1slot + rowoff + 4*pblk) =
                make_float4(wo0, wo1, wo2, wo3);
            __syncwarp();   // row g is quad-local (same warp)
            const ull* wv = (const ull*)(sW + l1slot + rowoff);
            ull a0 = 0ull, a1 = 0ull, a2 = 0ull, a3 = 0ull;
            #pragma unroll
            for (int c2 = 0; c2 < 8; c2++) {
                ull w = wv[c2];
                ffma2(a0, A2[0][c2], w);
                ffma2(a1, A2[1][c2], w);
                ffma2(a2, A2[2][c2], w);
                ffma2(a3, A2[3][c2], w);
            }
            const int mu = sxh[0];
            const float4 e4 = *(const float4*)(sBf + mu*256 + rowoff + 4*pblk);
            float s = (e4.x*unpack_sum(a0) + e4.y*unpack_sum(a1))
                    + (e4.z*unpack_sum(a2) + e4.w*unpack_sum(a3));
            s += __shfl_xor_sync(0xffffffffu, s, 1);
            s += __shfl_xor_sync(0xffffffffu, s, 2);
            accll += 0.25f * __log2f(s);
        }

        // ---- per-stream deterministic per-g reduction (8 threads share g) ----
        sacc[tid] = accll;
        HBAR(barid);
        if (tl < NG) {
            float s = 0.f;
            #pragma unroll
            for (int kk = 0; kk < 8; kk++)       // sng(2) x pblk(4)
                s += sacc[h*128 + (kk >> 2)*64 + tl*4 + (kk & 3)];
            // 127 internal nodes owe -1 each in log2 (folded BF=2 mean); to ln
            out[tree*NG + tl] = 0.69314718055994530942f * (s - 127.0f);
        }
        // loop-top HBAR protects sacc/sx/slots before next tree
    }
}

// ---------------------------------------------------------------------------
extern "C" void kernel_launch(void* const* d_in, const int* in_sizes, int n_in,
                              void* d_out, int out_size) {
    const float* A  = (const float*)d_in[0];
    const float* B  = (const float*)d_in[1];
    const float* Pi = (const float*)d_in[2];
    const int*   x  = (const int*)  d_in[3];
    float* out = (float*)d_out;

    cudaFuncSetAttribute(htmm_upward_kernel,
                         cudaFuncAttributeMaxDynamicSharedMemorySize, DYN_BYTES);

    htmm_softmax_kernel<<<1, 256>>>(A, B, Pi);
    htmm_upward_kernel<<<PGRID, 256, DYN_BYTES>>>(x, out);
}